// round 9
// baseline (speedup 1.0000x reference)
#include <cuda_runtime.h>

// Window_89696097010079 : Graves attention window  (B=256,T=2048,V=128,C=512,K=10)
// Inputs: x(B,C), kappa_old(B,K), onehots(B,T,V), W(3K,C), b(3K)  all f32
// Output: concat w(B,V) | kappa(B,K) | phi(B,T) -> 559616 f32
//
// Phase-4 (the 268 MB onehots stream) uses a 4-stage cp.async pipeline
// (16 KB chunks = 32 t-rows) so the copy engine, not warp scoreboards,
// sustains memory-level parallelism. Consumers FMA from smem.

#define Bn 256
#define Tn 2048
#define Vn 128
#define Cn 512
#define Kn 10

#define CH      32                    // t-rows per chunk
#define NCH     (Tn / CH)             // 64 chunks
#define NSTAGE  4
#define STAGE_F4 (CH * Vn / 4)        // 1024 float4 per stage
#define SMEM_FLOATS (32 + Tn + NSTAGE * STAGE_F4 * 4)   // params + phi + stages
#define SMEM_BYTES  (SMEM_FLOATS * 4)                   // 73856 B

__device__ __forceinline__ void cp_async16(float4* smem_dst, const float4* gsrc) {
    unsigned saddr = (unsigned)__cvta_generic_to_shared(smem_dst);
    asm volatile("cp.async.cg.shared.global [%0], [%1], 16;\n"
                 :: "r"(saddr), "l"(gsrc));
}
__device__ __forceinline__ void cp_commit() {
    asm volatile("cp.async.commit_group;\n" ::: "memory");
}
template<int N>
__device__ __forceinline__ void cp_wait() {
    asm volatile("cp.async.wait_group %0;\n" :: "n"(N) : "memory");
}

__global__ __launch_bounds__(512)
void window_fused_kernel(const float* __restrict__ x,
                         const float* __restrict__ kappa_old,
                         const float* __restrict__ onehots,
                         const float* __restrict__ W,
                         const float* __restrict__ bias,
                         float* __restrict__ out)
{
    extern __shared__ float smem[];
    float*  s_params = smem;            // 32 floats: [0,10)=alpha [10,20)=beta [20,30)=kappa
    float*  s_phi    = smem + 32;       // Tn floats
    float4* stages   = reinterpret_cast<float4*>(smem + 32 + Tn);  // NSTAGE * STAGE_F4
    float*  s_x      = reinterpret_cast<float*>(stages);           // alias (phase 1 only)
    float4* s_red    = reinterpret_cast<float4*>(stages);          // alias (final reduce)

    const int b   = blockIdx.x;
    const int tid = threadIdx.x;

    // ---- load x row into (aliased) smem ----
    s_x[tid] = x[(size_t)b * Cn + tid];
    __syncthreads();

    // ---- Phase 1+2: params = exp(x@W^T + b); kappa = kappa_old + pre_kappa ----
    if (tid < 480) {
        const int j   = tid >> 4;
        const int sub = tid & 15;
        const float* wrow = W + j * Cn + sub * 32;
        const float* xs   = s_x + sub * 32;
        float p0 = 0.f, p1 = 0.f, p2 = 0.f, p3 = 0.f;
        #pragma unroll
        for (int i = 0; i < 32; i += 4) {
            p0 = fmaf(xs[i + 0], wrow[i + 0], p0);
            p1 = fmaf(xs[i + 1], wrow[i + 1], p1);
            p2 = fmaf(xs[i + 2], wrow[i + 2], p2);
            p3 = fmaf(xs[i + 3], wrow[i + 3], p3);
        }
        float p = (p0 + p1) + (p2 + p3);
        p += __shfl_down_sync(0xffffffffu, p, 8, 16);
        p += __shfl_down_sync(0xffffffffu, p, 4, 16);
        p += __shfl_down_sync(0xffffffffu, p, 2, 16);
        p += __shfl_down_sync(0xffffffffu, p, 1, 16);
        if (sub == 0) {
            float v = expf(p + bias[j]);
            if (j >= 20) {
                v += kappa_old[b * Kn + (j - 20)];
                out[Bn * Vn + b * Kn + (j - 20)] = v;   // kappa output
            }
            s_params[j] = v;
        }
    }
    __syncthreads();   // after this, s_x (stage region) is free for cp.async

    // ---- Pipeline prologue: prefetch chunks 0..NSTAGE-2, overlapped with phi ----
    const float4* gsrc = reinterpret_cast<const float4*>(onehots + (size_t)b * Tn * Vn);
    #pragma unroll
    for (int c = 0; c < NSTAGE - 1; c++) {
        float4* st = stages + c * STAGE_F4;
        cp_async16(st + tid,        gsrc + (size_t)c * STAGE_F4 + tid);
        cp_async16(st + tid + 512,  gsrc + (size_t)c * STAGE_F4 + tid + 512);
        cp_commit();
    }

    // ---- Phase 3: phi (DMA of first chunks runs underneath this) ----
    float* out_phi = out + (size_t)Bn * Vn + Bn * Kn + (size_t)b * Tn;
    for (int t = tid; t < Tn; t += 512) {
        const float tf = (float)t;
        float acc = 0.f;
        #pragma unroll
        for (int k = 0; k < Kn; k++) {
            const float d = s_params[20 + k] - tf;
            acc = fmaf(s_params[k], expf(-s_params[10 + k] * d * d), acc);
        }
        s_phi[t] = acc;
        out_phi[t] = acc;
    }
    __syncthreads();

    // ---- Phase 4: pipelined w reduction ----
    const int v4 = tid & 31;   // lane -> float4 column within V
    const int ws = tid >> 5;   // warp -> t-row stripe within chunk (0..15)
    float4 acc0 = make_float4(0.f, 0.f, 0.f, 0.f);
    float4 acc1 = make_float4(0.f, 0.f, 0.f, 0.f);

    #pragma unroll 1
    for (int c = 0; c < NCH; c++) {
        // issue chunk c+NSTAGE-1 (empty commit keeps group accounting aligned)
        const int cn = c + NSTAGE - 1;
        if (cn < NCH) {
            float4* st = stages + (cn % NSTAGE) * STAGE_F4;
            cp_async16(st + tid,       gsrc + (size_t)cn * STAGE_F4 + tid);
            cp_async16(st + tid + 512, gsrc + (size_t)cn * STAGE_F4 + tid + 512);
        }
        cp_commit();
        cp_wait<NSTAGE - 1>();     // chunk c now resident
        __syncthreads();

        const float4* st = stages + (c % NSTAGE) * STAGE_F4;
        const int t0 = c * CH;
        // two t-rows per thread: ws and ws+16
        const float  pa = s_phi[t0 + ws];
        const float  pb = s_phi[t0 + ws + 16];
        const float4 oa = st[ws * 32 + v4];
        const float4 ob = st[(ws + 16) * 32 + v4];
        acc0.x = fmaf(pa, oa.x, acc0.x); acc0.y = fmaf(pa, oa.y, acc0.y);
        acc0.z = fmaf(pa, oa.z, acc0.z); acc0.w = fmaf(pa, oa.w, acc0.w);
        acc1.x = fmaf(pb, ob.x, acc1.x); acc1.y = fmaf(pb, ob.y, acc1.y);
        acc1.z = fmaf(pb, ob.z, acc1.z); acc1.w = fmaf(pb, ob.w, acc1.w);

        __syncthreads();           // stage may be overwritten next iteration
    }

    acc0.x += acc1.x; acc0.y += acc1.y; acc0.z += acc1.z; acc0.w += acc1.w;
    s_red[ws * 32 + v4] = acc0;    // aliases stage 0; all consumption done
    __syncthreads();

    if (tid < 32) {
        float4 r = s_red[tid];
        #pragma unroll
        for (int i = 1; i < 16; i++) {
            const float4 q = s_red[i * 32 + tid];
            r.x += q.x; r.y += q.y; r.z += q.z; r.w += q.w;
        }
        reinterpret_cast<float4*>(out + (size_t)b * Vn)[tid] = r;   // w output
    }
}

extern "C" void kernel_launch(void* const* d_in, const int* in_sizes, int n_in,
                              void* d_out, int out_size)
{
    (void)in_sizes; (void)n_in; (void)out_size;
    const float* x         = (const float*)d_in[0];
    const float* kappa_old = (const float*)d_in[1];
    const float* onehots   = (const float*)d_in[2];
    const float* W         = (const float*)d_in[3];
    const float* bias      = (const float*)d_in[4];
    float* out = (float*)d_out;

    cudaFuncSetAttribute(window_fused_kernel,
                         cudaFuncAttributeMaxDynamicSharedMemorySize, SMEM_BYTES);
    window_fused_kernel<<<Bn, 512, SMEM_BYTES>>>(x, kappa_old, onehots, W, bias, out);
}